// round 14
// baseline (speedup 1.0000x reference)
#include <cuda_runtime.h>
#include <cuda_bf16.h>
#include <cstdint>

#define BB    4
#define LQ    256
#define LK    2048
#define HIDD  1024
#define NH    16
#define DD    64
#define QT    16
#define NT    256
#define NCH   16                     /* chunks of 128 k */

#define CENTER_C      72.21632f
#define INV_SCALING_C 0.14662718f

/* smem float offsets: ring slot 8704 (K: 8192 used; V: 2 planes x 4352 u32) */
#define SLOT  8704
#define VPL   4352                   /* u32 per V plane (64 rows x 68) */
#define EOFF  17408                  /* e-stage ring 2 x (16 x 132) f32 */
#define ESLOT 2112
#define QOFF  21632
#define DOFF  22656
#define IVOFF 22720
#define PTOFF 22736
#define SMEMF (22800 * 4)            /* 91200 B -> 2 CTAs/SM */

typedef unsigned long long u64;
typedef unsigned int u32;
#define ABSM 0x7FFFFFFF7FFFFFFFULL

__device__ u32 g_VTh[(size_t)BB * NH * DD * LK / 2];  // V^T hi plane (bf16x2)
__device__ u32 g_VTl[(size_t)BB * NH * DD * LK / 2];  // V^T lo plane (bf16x2)

__device__ __forceinline__ u64 fadd2(u64 a, u64 b) {
    u64 r; asm("add.rn.f32x2 %0, %1, %2;" : "=l"(r) : "l"(a), "l"(b)); return r;
}
__device__ __forceinline__ u64 ffma2(u64 a, u64 b, u64 c) {
    u64 r; asm("fma.rn.f32x2 %0, %1, %2, %3;" : "=l"(r) : "l"(a), "l"(b), "l"(c)); return r;
}
__device__ __forceinline__ float2 upk2(u64 a) {
    float2 f; asm("mov.b64 {%0, %1}, %2;" : "=f"(f.x), "=f"(f.y) : "l"(a)); return f;
}
__device__ __forceinline__ u32 cvt2(float lo, float hi) {   // lo -> lower half
    u32 r; asm("cvt.rn.bf16x2.f32 %0, %1, %2;" : "=r"(r) : "f"(hi), "f"(lo)); return r;
}
__device__ __forceinline__ void split2(float x, float y, u32& h, u32& l) {
    h = cvt2(x, y);
    float xh = __uint_as_float(h << 16);
    float yh = __uint_as_float(h & 0xFFFF0000u);
    l = cvt2(x - xh, y - yh);
}
__device__ __forceinline__ void cp16(uint32_t dst, const void* src) {
    asm volatile("cp.async.cg.shared.global [%0], [%1], 16;" :: "r"(dst), "l"(src));
}
__device__ __forceinline__ void mma16816(float* c, const u32* a, const u32* b) {
    asm volatile(
        "mma.sync.aligned.m16n8k16.row.col.f32.bf16.bf16.f32 "
        "{%0,%1,%2,%3}, {%4,%5,%6,%7}, {%8,%9}, {%0,%1,%2,%3};"
        : "+f"(c[0]), "+f"(c[1]), "+f"(c[2]), "+f"(c[3])
        : "r"(a[0]), "r"(a[1]), "r"(a[2]), "r"(a[3]), "r"(b[0]), "r"(b[1]));
}

// ---------------------------------------------------------------------------
// Kernel 0: transpose V -> split-bf16 planes VTh/VTl [b,h,d,k].
// ---------------------------------------------------------------------------
__global__ __launch_bounds__(256) void k_vtrans(const float* __restrict__ Vg)
{
    __shared__ float t[64][65];
    const int bh = blockIdx.y, b = bh >> 4, h = bh & 15;
    const int k0 = blockIdx.x * 64;
    const int tid = threadIdx.x;
    #pragma unroll
    for (int r = 0; r < 4; r++) {
        int i = tid + 256 * r; int kr = i >> 4, g = i & 15;
        float4 v = *(const float4*)(Vg + ((size_t)(b * LK + k0 + kr)) * HIDD + h * DD + 4 * g);
        t[kr][4 * g + 0] = v.x; t[kr][4 * g + 1] = v.y;
        t[kr][4 * g + 2] = v.z; t[kr][4 * g + 3] = v.w;
    }
    __syncthreads();
    #pragma unroll
    for (int r = 0; r < 4; r++) {
        int i = tid + 256 * r; int d = i >> 4, g = i & 15;
        float4 o = make_float4(t[4 * g + 0][d], t[4 * g + 1][d], t[4 * g + 2][d], t[4 * g + 3][d]);
        u32 h01, l01, h23, l23;
        split2(o.x, o.y, h01, l01);
        split2(o.z, o.w, h23, l23);
        size_t idx = (size_t)(bh * DD + d) * (LK / 2) + (k0 + 4 * g) / 2;
        *(uint2*)(g_VTh + idx) = make_uint2(h01, h23);
        *(uint2*)(g_VTl + idx) = make_uint2(l01, l23);
    }
}

// ---------------------------------------------------------------------------
// Fused kernel: phase 1 = R8 champion (packed-f32x2 L1 distance, e->gmem);
// phase 2 = split-bf16 HMMA P@V (3 MMAs/tile, fp32 accumulate).
// grid (LQ/16, NH, BB), block 256 (8 warps), 91KB smem -> 2 CTAs/SM.
// ---------------------------------------------------------------------------
__global__ __launch_bounds__(NT, 2) void k_fused(
    const float* __restrict__ Qg, const float* __restrict__ Kg,
    const float* __restrict__ diag,
    float* __restrict__ attn, float* __restrict__ out0)
{
    extern __shared__ float smem[];
    float* estg0 = smem + EOFF;
    float* qbuf  = smem + QOFF;
    float* dbuf  = smem + DOFF;
    float* invs  = smem + IVOFF;
    float* part  = smem + PTOFF;

    const int b  = blockIdx.z, h = blockIdx.y;
    const int q0 = blockIdx.x * QT;
    const int tid = threadIdx.x, w = tid >> 5, lane = tid & 31;
    const int kg = w & 3, qg = w >> 2;          // phase-1 roles
    const int s  = lane & 7;
    const uint32_t sbase = (uint32_t)__cvta_generic_to_shared(smem);
    const uint32_t estg_b = sbase + EOFF * 4u;

    const size_t arow0 = (((size_t)(b * NH + h)) * LQ + q0) * (size_t)LK;

    // ---- prologue --------------------------------------------------------
    if (tid < 16)
        ((float4*)dbuf)[tid] = ((const float4*)(diag + h * DD))[tid];
    {
        int qr = tid >> 4, g = tid & 15;        // 16 rows x 16 f4, negated
        float4 v = ((const float4*)(Qg + ((size_t)(b * LQ + q0 + qr)) * HIDD + h * DD))[g];
        ((float4*)qbuf)[qr * 16 + g] = make_float4(-v.x, -v.y, -v.z, -v.w);
    }

    // prefetch K chunk 0 (XOR-swizzled f4 rows: 128 k-rows x 16 f4)
    #pragma unroll
    for (int r = 0; r < 8; r++) {
        int i = tid + NT * r; int kr = i >> 4, g = i & 15;
        cp16(sbase + (uint32_t)((kr * 16 + (g ^ (kr & 7))) * 16),
             ((const float4*)(Kg + ((size_t)(b * LK + kr)) * HIDD + h * DD)) + g);
    }
    asm volatile("cp.async.commit_group;");

    const ulonglong2* qb2 = (const ulonglong2*)qbuf;
    const ulonglong2* db2 = (const ulonglong2*)dbuf;
    float sume[8] = {0.f, 0.f, 0.f, 0.f, 0.f, 0.f, 0.f, 0.f};
    const int krow16 = (kg * 32 + lane) * 16;

    // ==== Phase 1: distance -> e -> attn (unnormalized) ===================
    for (int c = 0; c < NCH; c++) {
        asm volatile("cp.async.wait_group 0;");
        __syncthreads();

        if (c + 1 < NCH) {
            uint32_t boff = (uint32_t)(((c + 1) & 1) * (SLOT * 4));
            #pragma unroll
            for (int r = 0; r < 8; r++) {
                int i = tid + NT * r; int kr = i >> 4, g = i & 15;
                cp16(sbase + boff + (uint32_t)((kr * 16 + (g ^ (kr & 7))) * 16),
                     ((const float4*)(Kg + ((size_t)(b * LK + (c + 1) * 128 + kr)) * HIDD
                                      + h * DD)) + g);
            }
            asm volatile("cp.async.commit_group;");
        }

        const ulonglong2* kb2 = (const ulonglong2*)(smem + (c & 1) * SLOT);
        ulonglong2 kvr[16];
        #pragma unroll
        for (int g = 0; g < 16; g++) kvr[g] = kb2[krow16 + (g ^ s)];

        u64 acc[8];
        #pragma unroll
        for (int q = 0; q < 8; q++) acc[q] = 0ull;

        #pragma unroll
        for (int g = 0; g < 16; g++) {
            ulonglong2 dv = db2[g];                              // broadcast
            #pragma unroll
            for (int q = 0; q < 8; q++) {
                ulonglong2 qv = qb2[(qg * 8 + q) * 16 + g];      // broadcast
                u64 t0 = fadd2(kvr[g].x, qv.x) & ABSM;  // |k-q| (q pre-negated)
                u64 t1 = fadd2(kvr[g].y, qv.y) & ABSM;
                acc[q] = ffma2(dv.x, t0, acc[q]);
                acc[q] = ffma2(dv.y, t1, acc[q]);
            }
        }

        #pragma unroll
        for (int q = 0; q < 8; q++) {
            float2 a = upk2(acc[q]);
            float e = __expf((CENTER_C - (a.x + a.y)) * INV_SCALING_C);
            attn[arow0 + (size_t)(qg * 8 + q) * LK + c * 128 + kg * 32 + lane] = e;
            sume[q] += e;
        }
    }

    // softmax partial sums per (q, kg)
    #pragma unroll
    for (int q = 0; q < 8; q++) {
        float ssum = sume[q];
        #pragma unroll
        for (int o = 16; o > 0; o >>= 1) ssum += __shfl_xor_sync(0xffffffffu, ssum, o);
        if (lane == 0) part[(qg * 8 + q) * 4 + kg] = ssum;
    }
    __syncthreads();
    if (tid < 16)
        invs[tid] = 1.f / (part[tid * 4] + part[tid * 4 + 1] +
                           part[tid * 4 + 2] + part[tid * 4 + 3]);

    // prefetch V planes chunk 0 (u32 rows stride 68) + e chunk 0 (f32 stride 132)
    const u32* vth = g_VTh + (size_t)(b * NH + h) * DD * (LK / 2);
    const u32* vtl = g_VTl + (size_t)(b * NH + h) * DD * (LK / 2);
    #pragma unroll
    for (int r = 0; r < 4; r++) {
        int j = tid + NT * r; int d = j >> 4, seg = j & 15;
        cp16(sbase + (uint32_t)((d * 68 + seg * 4) * 4),
             vth + (size_t)d * (LK / 2) + seg * 4);
        cp16(sbase + (uint32_t)((VPL + d * 68 + seg * 4) * 4),
             vtl + (size_t)d * (LK / 2) + seg * 4);
    }
    #pragma unroll
    for (int r = 0; r < 2; r++) {
        int j = tid + NT * r; int qq = j >> 5, k4 = j & 31;
        cp16(estg_b + (uint32_t)((qq * 132 + 4 * k4) * 4),
             attn + arow0 + (size_t)qq * LK + 4 * k4);
    }
    asm volatile("cp.async.commit_group;");

    // ==== Phase 2: p write + split-bf16 HMMA P@V ==========================
    const int g2 = lane >> 2, t2 = lane & 3;    // mma group / quad-id
    const int n0 = w * 8;                       // this warp's d-slice
    float cacc[4] = {0.f, 0.f, 0.f, 0.f};

    for (int c = 0; c < NCH; c++) {
        int kc = c * 128;
        if (c + 1 < NCH) {
            uint32_t boff  = (uint32_t)(((c + 1) & 1) * (SLOT * 4));
            uint32_t boffe = (uint32_t)(((c + 1) & 1) * (ESLOT * 4));
            #pragma unroll
            for (int r = 0; r < 4; r++) {
                int j = tid + NT * r; int d = j >> 4, seg = j & 15;
                cp16(sbase + boff + (uint32_t)((d * 68 + seg * 4) * 4),
                     vth + (size_t)d * (LK / 2) + (kc + 128) / 2 + seg * 4);
                cp16(sbase + boff + (uint32_t)((VPL + d * 68 + seg * 4) * 4),
                     vtl + (size_t)d * (LK / 2) + (kc + 128) / 2 + seg * 4);
            }
            #pragma unroll
            for (int r = 0; r < 2; r++) {
                int j = tid + NT * r; int qq = j >> 5, k4 = j & 31;
                cp16(estg_b + boffe + (uint32_t)((qq * 132 + 4 * k4) * 4),
                     attn + arow0 + (size_t)qq * LK + kc + 128 + 4 * k4);
            }
            asm volatile("cp.async.commit_group;");
            asm volatile("cp.async.wait_group 1;");
        } else {
            asm volatile("cp.async.wait_group 0;");
        }
        __syncthreads();   // stage[c&1] ready; invs visible on c==0

        const float* estg = estg0 + (c & 1) * ESLOT;
        const u32* vhi = (const u32*)(smem + (c & 1) * SLOT);
        const u32* vlo = vhi + VPL;

        // write p = e * inv (coalesced STG.128)
        #pragma unroll
        for (int r = 0; r < 2; r++) {
            int j = tid + NT * r; int qq = j >> 5, k4 = j & 31;
            float4 e4 = *(const float4*)(estg + qq * 132 + 4 * k4);
            float iv = invs[qq];
            float4 p = make_float4(e4.x * iv, e4.y * iv, e4.z * iv, e4.w * iv);
            *(float4*)(attn + arow0 + (size_t)qq * LK + kc + 4 * k4) = p;
        }

        // HMMA: D[16q x 8d] += E[16q x 16k] * V[16k x 8d], 8 k-steps, 3 MMAs each
        const int vrow = (n0 + g2) * 68;
        #pragma unroll
        for (int ks = 0; ks < 8; ks++) {
            int kl = ks * 16;
            float2 ea0 = *(const float2*)(estg + g2 * 132 + kl + 2 * t2);
            float2 ea1 = *(const float2*)(estg + (g2 + 8) * 132 + kl + 2 * t2);
            float2 ea2 = *(const float2*)(estg + g2 * 132 + kl + 2 * t2 + 8);
            float2 ea3 = *(const float2*)(estg + (g2 + 8) * 132 + kl + 2 * t2 + 8);
            u32 ah[4], al[4];
            split2(ea0.x, ea0.y, ah[0], al[0]);
            split2(ea1.x, ea1.y, ah[1], al[1]);
            split2(ea2.x, ea2.y, ah[2], al[2]);
            split2(ea3.x, ea3.y, ah[3], al[3]);
            u32 bh[2] = { vhi[vrow + kl / 2 + t2], vhi[vrow + kl / 2 + t2 + 4] };
            u32 bl[2] = { vlo[vrow + kl / 2 + t2], vlo[vrow + kl / 2 + t2 + 4] };
            mma16816(cacc, ah, bh);
            mma16816(cacc, ah, bl);
            mma16816(cacc, al, bh);
        }
        __syncthreads();
    }

    // epilogue: scale by inv, store (lane -> q rows g2/g2+8, d cols n0+2t2..+1)
    {
        float iv0 = invs[g2], iv1 = invs[g2 + 8];
        size_t ob0 = ((size_t)(b * LQ + q0 + g2)) * HIDD + h * DD + n0 + 2 * t2;
        size_t ob1 = ((size_t)(b * LQ + q0 + g2 + 8)) * HIDD + h * DD + n0 + 2 * t2;
        *(float2*)(out0 + ob0) = make_float2(cacc[0] * iv0, cacc[1] * iv0);
        *(float2*)(out0 + ob1) = make_float2(cacc[2] * iv1, cacc[3] * iv1);
    }
}

extern "C" void kernel_launch(void* const* d_in, const int* in_sizes, int n_in,
                              void* d_out, int out_size)
{
    const float* Qg = (const float*)d_in[0];
    const float* Kg = (const float*)d_in[1];
    const float* Vg = (const float*)d_in[2];
    const float* dg = (const float*)d_in[3];

    float* out0 = (float*)d_out;
    float* attn = out0 + (size_t)BB * LQ * HIDD;   // (output, attention) concat

    cudaFuncSetAttribute(k_fused, cudaFuncAttributeMaxDynamicSharedMemorySize, SMEMF);

    k_vtrans<<<dim3(LK / 64, BB * NH), 256>>>(Vg);
    k_fused<<<dim3(LQ / QT, NH, BB), NT, SMEMF>>>(Qg, Kg, dg, attn, out0);
}

// round 16
// speedup vs baseline: 1.0323x; 1.0323x over previous
#include <cuda_runtime.h>
#include <cuda_bf16.h>
#include <cstdint>

#define BB    4
#define LQ    256
#define LK    2048
#define HIDD  1024
#define NH    16
#define DD    64
#define QT    16
#define NT    256
#define NCH   16                     /* chunks of 128 k */

#define CENTER_C      72.21632f
#define INV_SCALING_C 0.14662718f

/* smem 4B-word offsets */
#define SLOT  8704                   /* ring slot: K 8192 used / V 2 planes x 4352 u32 */
#define VPL   4352                   /* u32 per V plane (64 rows x 68) */
#define EOFF  17408                  /* e-stage ring 2 x 2112 f32 (16 x 132) */
#define ESLOT 2112
#define EBOFF 21632                  /* e bf16 planes ring 2 x 2176 u32 (hi 1088 | lo 1088) */
#define EBSLOT 2176
#define QOFF  25984
#define DOFF  27008
#define IVOFF 27072
#define PTOFF 27088
#define SMEMF (27152 * 4)            /* 108608 B -> 2 CTAs/SM */

typedef unsigned long long u64;
typedef unsigned int u32;
#define ABSM 0x7FFFFFFF7FFFFFFFULL

__device__ u32 g_VTh[(size_t)BB * NH * DD * LK / 2];  // V^T hi plane (bf16x2)
__device__ u32 g_VTl[(size_t)BB * NH * DD * LK / 2];  // V^T lo plane (bf16x2)

__device__ __forceinline__ u64 fadd2(u64 a, u64 b) {
    u64 r; asm("add.rn.f32x2 %0, %1, %2;" : "=l"(r) : "l"(a), "l"(b)); return r;
}
__device__ __forceinline__ u64 ffma2(u64 a, u64 b, u64 c) {
    u64 r; asm("fma.rn.f32x2 %0, %1, %2, %3;" : "=l"(r) : "l"(a), "l"(b), "l"(c)); return r;
}
__device__ __forceinline__ float2 upk2(u64 a) {
    float2 f; asm("mov.b64 {%0, %1}, %2;" : "=f"(f.x), "=f"(f.y) : "l"(a)); return f;
}
__device__ __forceinline__ u32 cvt2(float lo, float hi) {   // lo -> lower half
    u32 r; asm("cvt.rn.bf16x2.f32 %0, %1, %2;" : "=r"(r) : "f"(hi), "f"(lo)); return r;
}
__device__ __forceinline__ void split2(float x, float y, u32& h, u32& l) {
    h = cvt2(x, y);
    float xh = __uint_as_float(h << 16);
    float yh = __uint_as_float(h & 0xFFFF0000u);
    l = cvt2(x - xh, y - yh);
}
__device__ __forceinline__ void cp16(uint32_t dst, const void* src) {
    asm volatile("cp.async.cg.shared.global [%0], [%1], 16;" :: "r"(dst), "l"(src));
}
__device__ __forceinline__ void mma16816(float* c, const u32* a, const u32* b) {
    asm volatile(
        "mma.sync.aligned.m16n8k16.row.col.f32.bf16.bf16.f32 "
        "{%0,%1,%2,%3}, {%4,%5,%6,%7}, {%8,%9}, {%0,%1,%2,%3};"
        : "+f"(c[0]), "+f"(c[1]), "+f"(c[2]), "+f"(c[3])
        : "r"(a[0]), "r"(a[1]), "r"(a[2]), "r"(a[3]), "r"(b[0]), "r"(b[1]));
}
__device__ __forceinline__ void ldm4(u32* r, u32 addr) {
    asm volatile("ldmatrix.sync.aligned.m8n8.x4.shared.b16 {%0,%1,%2,%3}, [%4];"
        : "=r"(r[0]), "=r"(r[1]), "=r"(r[2]), "=r"(r[3]) : "r"(addr));
}

// ---------------------------------------------------------------------------
// Kernel 0: transpose V -> split-bf16 planes VTh/VTl [b,h,d,k].
// ---------------------------------------------------------------------------
__global__ __launch_bounds__(256) void k_vtrans(const float* __restrict__ Vg)
{
    __shared__ float t[64][65];
    const int bh = blockIdx.y, b = bh >> 4, h = bh & 15;
    const int k0 = blockIdx.x * 64;
    const int tid = threadIdx.x;
    #pragma unroll
    for (int r = 0; r < 4; r++) {
        int i = tid + 256 * r; int kr = i >> 4, g = i & 15;
        float4 v = *(const float4*)(Vg + ((size_t)(b * LK + k0 + kr)) * HIDD + h * DD + 4 * g);
        t[kr][4 * g + 0] = v.x; t[kr][4 * g + 1] = v.y;
        t[kr][4 * g + 2] = v.z; t[kr][4 * g + 3] = v.w;
    }
    __syncthreads();
    #pragma unroll
    for (int r = 0; r < 4; r++) {
        int i = tid + 256 * r; int d = i >> 4, g = i & 15;
        float4 o = make_float4(t[4 * g + 0][d], t[4 * g + 1][d], t[4 * g + 2][d], t[4 * g + 3][d]);
        u32 h01, l01, h23, l23;
        split2(o.x, o.y, h01, l01);
        split2(o.z, o.w, h23, l23);
        size_t idx = (size_t)(bh * DD + d) * (LK / 2) + (k0 + 4 * g) / 2;
        *(uint2*)(g_VTh + idx) = make_uint2(h01, h23);
        *(uint2*)(g_VTl + idx) = make_uint2(l01, l23);
    }
}

// ---------------------------------------------------------------------------
// Fused kernel: phase 1 = R8 champion (packed-f32x2 L1 distance, e->gmem);
// phase 2 = split-bf16 HMMA P@V, cooperative e-split + ldmatrix A-frags.
// Prefetch for slot s is issued ONLY after the top barrier of the iteration,
// which guarantees all warps finished the previous iteration's HMMA reads of
// slot s (fixes R15's WAR race). grid (LQ/16, NH, BB), block 256, 2 CTAs/SM.
// ---------------------------------------------------------------------------
__global__ __launch_bounds__(NT, 2) void k_fused(
    const float* __restrict__ Qg, const float* __restrict__ Kg,
    const float* __restrict__ diag,
    float* __restrict__ attn, float* __restrict__ out0)
{
    extern __shared__ float smem[];
    float* estg0 = smem + EOFF;
    float* qbuf  = smem + QOFF;
    float* dbuf  = smem + DOFF;
    float* invs  = smem + IVOFF;
    float* part  = smem + PTOFF;

    const int b  = blockIdx.z, h = blockIdx.y;
    const int q0 = blockIdx.x * QT;
    const int tid = threadIdx.x, w = tid >> 5, lane = tid & 31;
    const int kg = w & 3, qg = w >> 2;          // phase-1 roles
    const int s  = lane & 7;
    const uint32_t sbase = (uint32_t)__cvta_generic_to_shared(smem);
    const uint32_t estg_b = sbase + EOFF * 4u;

    const size_t arow0 = (((size_t)(b * NH + h)) * LQ + q0) * (size_t)LK;

    // ---- prologue --------------------------------------------------------
    if (tid < 16)
        ((float4*)dbuf)[tid] = ((const float4*)(diag + h * DD))[tid];
    {
        int qr = tid >> 4, g = tid & 15;        // 16 rows x 16 f4, negated
        float4 v = ((const float4*)(Qg + ((size_t)(b * LQ + q0 + qr)) * HIDD + h * DD))[g];
        ((float4*)qbuf)[qr * 16 + g] = make_float4(-v.x, -v.y, -v.z, -v.w);
    }

    // prefetch K chunk 0 (XOR-swizzled f4 rows: 128 k-rows x 16 f4)
    #pragma unroll
    for (int r = 0; r < 8; r++) {
        int i = tid + NT * r; int kr = i >> 4, g = i & 15;
        cp16(sbase + (uint32_t)((kr * 16 + (g ^ (kr & 7))) * 16),
             ((const float4*)(Kg + ((size_t)(b * LK + kr)) * HIDD + h * DD)) + g);
    }
    asm volatile("cp.async.commit_group;");

    const ulonglong2* qb2 = (const ulonglong2*)qbuf;
    const ulonglong2* db2 = (const ulonglong2*)dbuf;
    float sume[8] = {0.f, 0.f, 0.f, 0.f, 0.f, 0.f, 0.f, 0.f};
    const int krow16 = (kg * 32 + lane) * 16;

    // ==== Phase 1: distance -> e -> attn (unnormalized) ===================
    for (int c = 0; c < NCH; c++) {
        asm volatile("cp.async.wait_group 0;");
        __syncthreads();

        if (c + 1 < NCH) {
            uint32_t boff = (uint32_t)(((c + 1) & 1) * (SLOT * 4));
            #pragma unroll
            for (int r = 0; r < 8; r++) {
                int i = tid + NT * r; int kr = i >> 4, g = i & 15;
                cp16(sbase + boff + (uint32_t)((kr * 16 + (g ^ (kr & 7))) * 16),
                     ((const float4*)(Kg + ((size_t)(b * LK + (c + 1) * 128 + kr)) * HIDD
                                      + h * DD)) + g);
            }
            asm volatile("cp.async.commit_group;");
        }

        const ulonglong2* kb2 = (const ulonglong2*)(smem + (c & 1) * SLOT);
        ulonglong2 kvr[16];
        #pragma unroll
        for (int g = 0; g < 16; g++) kvr[g] = kb2[krow16 + (g ^ s)];

        u64 acc[8];
        #pragma unroll
        for (int q = 0; q < 8; q++) acc[q] = 0ull;

        #pragma unroll
        for (int g = 0; g < 16; g++) {
            ulonglong2 dv = db2[g];                              // broadcast
            #pragma unroll
            for (int q = 0; q < 8; q++) {
                ulonglong2 qv = qb2[(qg * 8 + q) * 16 + g];      // broadcast
                u64 t0 = fadd2(kvr[g].x, qv.x) & ABSM;  // |k-q| (q pre-negated)
                u64 t1 = fadd2(kvr[g].y, qv.y) & ABSM;
                acc[q] = ffma2(dv.x, t0, acc[q]);
                acc[q] = ffma2(dv.y, t1, acc[q]);
            }
        }

        #pragma unroll
        for (int q = 0; q < 8; q++) {
            float2 a = upk2(acc[q]);
            float e = __expf((CENTER_C - (a.x + a.y)) * INV_SCALING_C);
            attn[arow0 + (size_t)(qg * 8 + q) * LK + c * 128 + kg * 32 + lane] = e;
            sume[q] += e;
        }
    }

    // softmax partial sums per (q, kg)
    #pragma unroll
    for (int q = 0; q < 8; q++) {
        float ssum = sume[q];
        #pragma unroll
        for (int o = 16; o > 0; o >>= 1) ssum += __shfl_xor_sync(0xffffffffu, ssum, o);
        if (lane == 0) part[(qg * 8 + q) * 4 + kg] = ssum;
    }
    __syncthreads();
    if (tid < 16)
        invs[tid] = 1.f / (part[tid * 4] + part[tid * 4 + 1] +
                           part[tid * 4 + 2] + part[tid * 4 + 3]);

    // prefetch V planes chunk 0 (u32 rows stride 68) + e chunk 0 (f32 stride 132)
    const u32* vth = g_VTh + (size_t)(b * NH + h) * DD * (LK / 2);
    const u32* vtl = g_VTl + (size_t)(b * NH + h) * DD * (LK / 2);
    #pragma unroll
    for (int r = 0; r < 4; r++) {
        int j = tid + NT * r; int d = j >> 4, seg = j & 15;
        cp16(sbase + (uint32_t)((d * 68 + seg * 4) * 4),
             vth + (size_t)d * (LK / 2) + seg * 4);
        cp16(sbase + (uint32_t)((VPL + d * 68 + seg * 4) * 4),
             vtl + (size_t)d * (LK / 2) + seg * 4);
    }
    #pragma unroll
    for (int r = 0; r < 2; r++) {
        int j = tid + NT * r; int qq = j >> 5, k4 = j & 31;
        cp16(estg_b + (uint32_t)((qq * 132 + 4 * k4) * 4),
             attn + arow0 + (size_t)qq * LK + 4 * k4);
    }
    asm volatile("cp.async.commit_group;");

    // ==== Phase 2: p write + e-split + ldmatrix HMMA P@V ==================
    const int g2 = lane >> 2, t2 = lane & 3;    // mma group / quad-id
    const int n0 = w * 8;                       // this warp's d-slice
    const int sqq = tid >> 4, sseg = tid & 15;  // split-pass roles
    float cacc[4] = {0.f, 0.f, 0.f, 0.f};
    // ldmatrix lane base (bytes): row (lane&15) stride 272B, col-half (lane>>4)*16B
    const u32 lmoff = (u32)((lane & 15) * 272 + (lane >> 4) * 16);

    for (int c = 0; c < NCH; c++) {
        int kc = c * 128;
        asm volatile("cp.async.wait_group 0;");
        __syncthreads();   // slot[c&1] ready AND all warps done reading slot[(c+1)&1]

        // prefetch next chunk (safe: top barrier ordered prior HMMA reads)
        if (c + 1 < NCH) {
            uint32_t boff  = (uint32_t)(((c + 1) & 1) * (SLOT * 4));
            uint32_t boffe = (uint32_t)(((c + 1) & 1) * (ESLOT * 4));
            #pragma unroll
            for (int r = 0; r < 4; r++) {
                int j = tid + NT * r; int d = j >> 4, seg = j & 15;
                cp16(sbase + boff + (uint32_t)((d * 68 + seg * 4) * 4),
                     vth + (size_t)d * (LK / 2) + (kc + 128) / 2 + seg * 4);
                cp16(sbase + boff + (uint32_t)((VPL + d * 68 + seg * 4) * 4),
                     vtl + (size_t)d * (LK / 2) + (kc + 128) / 2 + seg * 4);
            }
            #pragma unroll
            for (int r = 0; r < 2; r++) {
                int j = tid + NT * r; int qq = j >> 5, k4 = j & 31;
                cp16(estg_b + boffe + (uint32_t)((qq * 132 + 4 * k4) * 4),
                     attn + arow0 + (size_t)qq * LK + kc + 128 + 4 * k4);
            }
            asm volatile("cp.async.commit_group;");
        }

        const float* estg = estg0 + (c & 1) * ESLOT;
        u32* ebh = (u32*)(smem + EBOFF) + (c & 1) * EBSLOT;

        // cooperative split: 8 e-elems per thread -> bf16 hi/lo planes
        {
            const float* ep = estg + sqq * 132 + sseg * 8;
            float4 e0 = *(const float4*)ep;
            float4 e1 = *(const float4*)(ep + 4);
            u32 h0, l0, h1, l1, h2, l2, h3, l3;
            split2(e0.x, e0.y, h0, l0); split2(e0.z, e0.w, h1, l1);
            split2(e1.x, e1.y, h2, l2); split2(e1.z, e1.w, h3, l3);
            *(uint4*)(ebh + sqq * 68 + sseg * 4)        = make_uint4(h0, h1, h2, h3);
            *(uint4*)(ebh + 1088 + sqq * 68 + sseg * 4) = make_uint4(l0, l1, l2, l3);
        }

        // write p = e * inv (coalesced STG.128)
        #pragma unroll
        for (int r = 0; r < 2; r++) {
            int j = tid + NT * r; int qq = j >> 5, k4 = j & 31;
            float4 e4 = *(const float4*)(estg + qq * 132 + 4 * k4);
            float iv = invs[qq];
            float4 p = make_float4(e4.x * iv, e4.y * iv, e4.z * iv, e4.w * iv);
            *(float4*)(attn + arow0 + (size_t)qq * LK + kc + 4 * k4) = p;
        }
        __syncthreads();   // planes[c&1] populated

        // HMMA: D[16q x 8d] += E[16q x 16k] * V[16k x 8d], 8 k-steps, 3 MMAs each
        const u32* vhi = (const u32*)(smem + (c & 1) * SLOT);
        const u32* vlo = vhi + VPL;
        const int vrow = (n0 + g2) * 68;
        const u32 abase_h = sbase + (u32)((EBOFF + (c & 1) * EBSLOT) * 4) + lmoff;
        const u32 abase_l = abase_h + 1088u * 4u;
        #pragma unroll
        for (int ks = 0; ks < 8; ks++) {
            u32 ah[4], al[4];
            ldm4(ah, abase_h + ks * 32);
            ldm4(al, abase_l + ks * 32);
            u32 bh[2] = { vhi[vrow + ks * 8 + t2], vhi[vrow + ks * 8 + t2 + 4] };
            u32 bl[2] = { vlo[vrow + ks * 8 + t2], vlo[vrow + ks * 8 + t2 + 4] };
            mma16816(cacc, ah, bh);
            mma16816(cacc, ah, bl);
            mma16816(cacc, al, bh);
        }
        // no trailing barrier: next iteration's top barrier orders the WAR
    }

    // epilogue: scale by inv, store (lane -> q rows g2/g2+8, d cols n0+2t2..+1)
    {
        float iv0 = invs[g2], iv1 = invs[g2 + 8];
        size_t ob0 = ((size_t)(b * LQ + q0 + g2)) * HIDD + h * DD + n0 + 2 * t2;
        size_t ob1 = ((size_t)(b * LQ + q0 + g2 + 8)) * HIDD + h * DD + n0 + 2 * t2;
        *(float2*)(out0 + ob0) = make_float2(cacc[0] * iv0, cacc[1] * iv0);
        *(float2*)(out0 + ob1) = make_float2(cacc[2] * iv1, cacc[3] * iv1);
    }
}

extern "C" void kernel_launch(void* const* d_in, const int* in_sizes, int n_in,
                              void* d_out, int out_size)
{
    const float* Qg = (const float*)d_in[0];
    const float* Kg = (const float*)d_in[1];
    const float* Vg = (const float*)d_in[2];
    const float* dg = (const float*)d_in[3];

    float* out0 = (float*)d_out;
    float* attn = out0 + (size_t)BB * LQ * HIDD;   // (output, attention) concat

    cudaFuncSetAttribute(k_fused, cudaFuncAttributeMaxDynamicSharedMemorySize, SMEMF);

    k_vtrans<<<dim3(LK / 64, BB * NH), 256>>>(Vg);
    k_fused<<<dim3(LQ / QT, NH, BB), NT, SMEMF>>>(Qg, Kg, dg, attn, out0);
}

// round 17
// speedup vs baseline: 1.0392x; 1.0066x over previous
#include <cuda_runtime.h>
#include <cuda_bf16.h>
#include <cstdint>

#define BB    4
#define LQ    256
#define LK    2048
#define HIDD  1024
#define NH    16
#define DD    64
#define QT    16
#define NT    256
#define NCH   16                     /* chunks of 128 k */

#define CENTER_C      72.21632f
#define INV_SCALING_C 0.14662718f

/* smem 4B-word offsets */
#define KR0   0                      /* K ring 2 x 8192 */
#define VHOFF 16384                  /* V hi plane 4352 u32 (64 rows x 68) */
#define VLOFF 20736                  /* V lo plane 4352 u32 */
#define EHOFF 25088                  /* e hi plane 1088 u32 (16 rows x 68) */
#define ELOFF 26176                  /* e lo plane 1088 u32 */
#define QOFF  27264                  /* qbuf 1024 */
#define DOFF  28288                  /* dbuf 64 */
#define IVOFF 28352                  /* invs 16 */
#define PTOFF 28368                  /* part 64 */
#define SMEMF (28432 * 4)            /* 113728 B -> 2 CTAs/SM */

typedef unsigned long long u64;
typedef unsigned int u32;
#define ABSM 0x7FFFFFFF7FFFFFFFULL

__device__ u32 g_VTh[(size_t)BB * NH * DD * LK / 2];  // V^T hi plane (bf16x2)
__device__ u32 g_VTl[(size_t)BB * NH * DD * LK / 2];  // V^T lo plane (bf16x2)

__device__ __forceinline__ u64 fadd2(u64 a, u64 b) {
    u64 r; asm("add.rn.f32x2 %0, %1, %2;" : "=l"(r) : "l"(a), "l"(b)); return r;
}
__device__ __forceinline__ u64 ffma2(u64 a, u64 b, u64 c) {
    u64 r; asm("fma.rn.f32x2 %0, %1, %2, %3;" : "=l"(r) : "l"(a), "l"(b), "l"(c)); return r;
}
__device__ __forceinline__ float2 upk2(u64 a) {
    float2 f; asm("mov.b64 {%0, %1}, %2;" : "=f"(f.x), "=f"(f.y) : "l"(a)); return f;
}
__device__ __forceinline__ u32 cvt2(float lo, float hi) {   // lo -> lower half
    u32 r; asm("cvt.rn.bf16x2.f32 %0, %1, %2;" : "=r"(r) : "f"(hi), "f"(lo)); return r;
}
__device__ __forceinline__ void split2(float x, float y, u32& h, u32& l) {
    h = cvt2(x, y);
    float xh = __uint_as_float(h << 16);
    float yh = __uint_as_float(h & 0xFFFF0000u);
    l = cvt2(x - xh, y - yh);
}
// scalar split: x -> bf16 hi bits (u16 in low half) + bf16 lo bits
__device__ __forceinline__ void split1(float x, unsigned short& hs, unsigned short& ls) {
    asm("cvt.rn.bf16.f32 %0, %1;" : "=h"(hs) : "f"(x));
    float hf = __uint_as_float(((u32)hs) << 16);
    float res = x - hf;
    asm("cvt.rn.bf16.f32 %0, %1;" : "=h"(ls) : "f"(res));
}
__device__ __forceinline__ void cp16(uint32_t dst, const void* src) {
    asm volatile("cp.async.cg.shared.global [%0], [%1], 16;" :: "r"(dst), "l"(src));
}
__device__ __forceinline__ void sts16(uint32_t addr, unsigned short v) {
    asm volatile("st.shared.u16 [%0], %1;" :: "r"(addr), "h"(v));
}
__device__ __forceinline__ void mma16816(float* c, const u32* a, const u32* b) {
    asm volatile(
        "mma.sync.aligned.m16n8k16.row.col.f32.bf16.bf16.f32 "
        "{%0,%1,%2,%3}, {%4,%5,%6,%7}, {%8,%9}, {%0,%1,%2,%3};"
        : "+f"(c[0]), "+f"(c[1]), "+f"(c[2]), "+f"(c[3])
        : "r"(a[0]), "r"(a[1]), "r"(a[2]), "r"(a[3]), "r"(b[0]), "r"(b[1]));
}
__device__ __forceinline__ void ldm4(u32* r, u32 addr) {
    asm volatile("ldmatrix.sync.aligned.m8n8.x4.shared.b16 {%0,%1,%2,%3}, [%4];"
        : "=r"(r[0]), "=r"(r[1]), "=r"(r[2]), "=r"(r[3]) : "r"(addr));
}

// ---------------------------------------------------------------------------
// Kernel 0: transpose V -> split-bf16 planes VTh/VTl [b,h,d,k].
// ---------------------------------------------------------------------------
__global__ __launch_bounds__(256) void k_vtrans(const float* __restrict__ Vg)
{
    __shared__ float t[64][65];
    const int bh = blockIdx.y, b = bh >> 4, h = bh & 15;
    const int k0 = blockIdx.x * 64;
    const int tid = threadIdx.x;
    #pragma unroll
    for (int r = 0; r < 4; r++) {
        int i = tid + 256 * r; int kr = i >> 4, g = i & 15;
        float4 v = *(const float4*)(Vg + ((size_t)(b * LK + k0 + kr)) * HIDD + h * DD + 4 * g);
        t[kr][4 * g + 0] = v.x; t[kr][4 * g + 1] = v.y;
        t[kr][4 * g + 2] = v.z; t[kr][4 * g + 3] = v.w;
    }
    __syncthreads();
    #pragma unroll
    for (int r = 0; r < 4; r++) {
        int i = tid + 256 * r; int d = i >> 4, g = i & 15;
        float4 o = make_float4(t[4 * g + 0][d], t[4 * g + 1][d], t[4 * g + 2][d], t[4 * g + 3][d]);
        u32 h01, l01, h23, l23;
        split2(o.x, o.y, h01, l01);
        split2(o.z, o.w, h23, l23);
        size_t idx = (size_t)(bh * DD + d) * (LK / 2) + (k0 + 4 * g) / 2;
        *(uint2*)(g_VTh + idx) = make_uint2(h01, h23);
        *(uint2*)(g_VTl + idx) = make_uint2(l01, l23);
    }
}

// ---------------------------------------------------------------------------
// Merged single-pass kernel: per chunk -> distance/e (champion math) -> e STG
// + e split-bf16 STS -> HMMA P@V accumulate. Tail: inv, p-sweep, out0 store.
// grid (LQ/16, NH, BB), block 256 (8 warps), 113.7KB smem -> 2 CTAs/SM.
// ---------------------------------------------------------------------------
__global__ __launch_bounds__(NT, 2) void k_fused(
    const float* __restrict__ Qg, const float* __restrict__ Kg,
    const float* __restrict__ diag,
    float* __restrict__ attn, float* __restrict__ out0)
{
    extern __shared__ float smem[];
    float* qbuf = smem + QOFF;
    float* dbuf = smem + DOFF;
    float* invs = smem + IVOFF;
    float* part = smem + PTOFF;

    const int b  = blockIdx.z, h = blockIdx.y;
    const int q0 = blockIdx.x * QT;
    const int tid = threadIdx.x, w = tid >> 5, lane = tid & 31;
    const int kg = w & 3, qg = w >> 2;          // distance roles
    const int s  = lane & 7;
    const uint32_t sbase = (uint32_t)__cvta_generic_to_shared(smem);

    const size_t arow0 = (((size_t)(b * NH + h)) * LQ + q0) * (size_t)LK;

    // ---- prologue --------------------------------------------------------
    if (tid < 16)
        ((float4*)dbuf)[tid] = ((const float4*)(diag + h * DD))[tid];
    {
        int qr = tid >> 4, g = tid & 15;        // 16 rows x 16 f4, negated
        float4 v = ((const float4*)(Qg + ((size_t)(b * LQ + q0 + qr)) * HIDD + h * DD))[g];
        ((float4*)qbuf)[qr * 16 + g] = make_float4(-v.x, -v.y, -v.z, -v.w);
    }

    // prefetch K chunk 0 (XOR-swizzled f4 rows: 128 k-rows x 16 f4)
    #pragma unroll
    for (int r = 0; r < 8; r++) {
        int i = tid + NT * r; int kr = i >> 4, g = i & 15;
        cp16(sbase + (uint32_t)((kr * 16 + (g ^ (kr & 7))) * 16),
             ((const float4*)(Kg + ((size_t)(b * LK + kr)) * HIDD + h * DD)) + g);
    }
    asm volatile("cp.async.commit_group;");

    const ulonglong2* qb2 = (const ulonglong2*)qbuf;
    const ulonglong2* db2 = (const ulonglong2*)dbuf;
    const u32* vth = g_VTh + (size_t)(b * NH + h) * DD * (LK / 2);
    const u32* vtl = g_VTl + (size_t)(b * NH + h) * DD * (LK / 2);

    float sume[8] = {0.f, 0.f, 0.f, 0.f, 0.f, 0.f, 0.f, 0.f};
    const int krow16 = (kg * 32 + lane) * 16;

    // HMMA roles
    const int g2 = lane >> 2, t2 = lane & 3;
    const int n0 = w * 8;                       // this warp's d-slice
    float cacc[4] = {0.f, 0.f, 0.f, 0.f};
    const u32 lmoff = (u32)((lane & 15) * 272 + (lane >> 4) * 16);
    const u32 abase_h = sbase + EHOFF * 4u + lmoff;
    const u32 abase_l = sbase + ELOFF * 4u + lmoff;
    // e split-STS base (bytes) for this thread's column
    const u32 ecol = (u32)(kg * 32 + lane);
    const u32 esth = sbase + EHOFF * 4u + ecol * 2u;
    const u32 estl = sbase + ELOFF * 4u + ecol * 2u;

    // ==== merged chunk loop ===============================================
    for (int c = 0; c < NCH; c++) {
        asm volatile("cp.async.wait_group 0;");
        __syncthreads();   // K(c) ready; e-slot/V/K(c-1) slot reads all done

        // issue V(c) into single V buffer (group V), then K(c+1) (group K)
        #pragma unroll
        for (int r = 0; r < 4; r++) {
            int j = tid + NT * r; int d = j >> 4, seg = j & 15;
            cp16(sbase + (uint32_t)((VHOFF + d * 68 + seg * 4) * 4),
                 vth + (size_t)d * (LK / 2) + c * 64 + seg * 4);
            cp16(sbase + (uint32_t)((VLOFF + d * 68 + seg * 4) * 4),
                 vtl + (size_t)d * (LK / 2) + c * 64 + seg * 4);
        }
        asm volatile("cp.async.commit_group;");
        if (c + 1 < NCH) {
            uint32_t boff = (uint32_t)(((c + 1) & 1) * 32768);
            #pragma unroll
            for (int r = 0; r < 8; r++) {
                int i = tid + NT * r; int kr = i >> 4, g = i & 15;
                cp16(sbase + boff + (uint32_t)((kr * 16 + (g ^ (kr & 7))) * 16),
                     ((const float4*)(Kg + ((size_t)(b * LK + (c + 1) * 128 + kr)) * HIDD
                                      + h * DD)) + g);
            }
            asm volatile("cp.async.commit_group;");
        }

        // distance math (champion form)
        const ulonglong2* kb2 = (const ulonglong2*)(smem + (c & 1) * 8192);
        ulonglong2 kvr[16];
        #pragma unroll
        for (int g = 0; g < 16; g++) kvr[g] = kb2[krow16 + (g ^ s)];

        u64 acc[8];
        #pragma unroll
        for (int q = 0; q < 8; q++) acc[q] = 0ull;

        #pragma unroll
        for (int g = 0; g < 16; g++) {
            ulonglong2 dv = db2[g];                              // broadcast
            #pragma unroll
            for (int q = 0; q < 8; q++) {
                ulonglong2 qv = qb2[(qg * 8 + q) * 16 + g];      // broadcast
                u64 t0 = fadd2(kvr[g].x, qv.x) & ABSM;  // |k-q| (q pre-negated)
                u64 t1 = fadd2(kvr[g].y, qv.y) & ABSM;
                acc[q] = ffma2(dv.x, t0, acc[q]);
                acc[q] = ffma2(dv.y, t1, acc[q]);
            }
        }

        // e: STG to attn (unnormalized) + split-bf16 STS into e-slot
        #pragma unroll
        for (int q = 0; q < 8; q++) {
            float2 a = upk2(acc[q]);
            float e = __expf((CENTER_C - (a.x + a.y)) * INV_SCALING_C);
            attn[arow0 + (size_t)(qg * 8 + q) * LK + c * 128 + kg * 32 + lane] = e;
            sume[q] += e;
            unsigned short hs, ls;
            split1(e, hs, ls);
            sts16(esth + (u32)(qg * 8 + q) * 272u, hs);
            sts16(estl + (u32)(qg * 8 + q) * 272u, ls);
        }

        asm volatile("cp.async.wait_group %0;" :: "n"(1));  // V(c) arrived (K(c+1) may fly)
        __syncthreads();   // e-slot complete from all warps

        // HMMA: D[16q x 8d] += E[16q x 16k] * V[16k x 8d], 8 k-steps, 3 MMAs each
        const u32* vhi = (const u32*)(smem + VHOFF);
        const u32* vlo = (const u32*)(smem + VLOFF);
        const int vrow = (n0 + g2) * 68;
        #pragma unroll
        for (int ks = 0; ks < 8; ks++) {
            u32 ah[4], al[4];
            ldm4(ah, abase_h + ks * 32);
            ldm4(al, abase_l + ks * 32);
            u32 bh[2] = { vhi[vrow + ks * 8 + t2], vhi[vrow + ks * 8 + t2 + 4] };
            u32 bl[2] = { vlo[vrow + ks * 8 + t2], vlo[vrow + ks * 8 + t2 + 4] };
            mma16816(cacc, ah, bh);
            mma16816(cacc, ah, bl);
            mma16816(cacc, al, bh);
        }
        // no trailing barrier: next iteration's top barrier orders the WAR
    }

    // ==== softmax inv ======================================================
    #pragma unroll
    for (int q = 0; q < 8; q++) {
        float ssum = sume[q];
        #pragma unroll
        for (int o = 16; o > 0; o >>= 1) ssum += __shfl_xor_sync(0xffffffffu, ssum, o);
        if (lane == 0) part[(qg * 8 + q) * 4 + kg] = ssum;
    }
    __syncthreads();   // also orders all e STGs (bar.sync implies membar.cta)
    if (tid < 16)
        invs[tid] = 1.f / (part[tid * 4] + part[tid * 4 + 1] +
                           part[tid * 4 + 2] + part[tid * 4 + 3]);
    __syncthreads();

    // ==== tail: p = e * inv sweep (L2-hot, coalesced) ======================
    #pragma unroll 8
    for (int r = 0; r < 32; r++) {
        int j = tid + NT * r;                 // 0..8191 f4 indices
        int qq = j >> 9;                      // 512 f4 per q row
        size_t idx = arow0 + (size_t)qq * LK + (size_t)(j & 511) * 4;
        float4 e4 = *(const float4*)(attn + idx);
        float iv = invs[qq];
        *(float4*)(attn + idx) = make_float4(e4.x * iv, e4.y * iv, e4.z * iv, e4.w * iv);
    }

    // ==== epilogue: out0 = cacc * inv =====================================
    {
        float iv0 = invs[g2], iv1 = invs[g2 + 8];
        size_t ob0 = ((size_t)(b * LQ + q0 + g2)) * HIDD + h * DD + n0 + 2 * t2;
        size_t ob1 = ((size_t)(b * LQ + q0 + g2 + 8)) * HIDD + h * DD + n0 + 2 * t2;
        *(float2*)(out0 + ob0) = make_float2(cacc[0] * iv0, cacc[1] * iv0);
        *(float2*)(out0 + ob1) = make_float2(cacc[2] * iv1, cacc[3] * iv1);
    }
}

extern "C" void kernel_launch(void* const* d_in, const int* in_sizes, int n_in,
                              void* d_out, int out_size)
{
    const float* Qg = (const float*)d_in[0];
    const float* Kg = (const float*)d_in[1];
    const float* Vg = (const float*)d_in[2];
    const float* dg = (const float*)d_in[3];

    float* out0 = (float*)d_out;
    float* attn = out0 + (size_t)BB * LQ * HIDD;   // (output, attention) concat

    cudaFuncSetAttribute(k_fused, cudaFuncAttributeMaxDynamicSharedMemorySize, SMEMF);

    k_vtrans<<<dim3(LK / 64, BB * NH), 256>>>(Vg);
    k_fused<<<dim3(LQ / QT, NH, BB), NT, SMEMF>>>(Qg, Kg, dg, attn, out0);
}